// round 1
// baseline (speedup 1.0000x reference)
#include <cuda_runtime.h>
#include <cstdint>

// Problem constants (match reference setup_inputs)
#define N_SLOTS_MAX 65536
#define DIM 128

#define UPDATE_RATE 0.1f
#define ONE_MINUS_MOMENTUM 0.1f
#define MOMENTUM 0.9f
#define GATE_THRESH 0.01f

// Scratch: per-slot weighted counts (256 KB). __device__ global — no allocation.
__device__ float g_counts[N_SLOTS_MAX];

// ---------------------------------------------------------------------------
// Kernel 1: zero the counts array
// ---------------------------------------------------------------------------
__global__ void k_zero_counts(int n_slots) {
    int i = blockIdx.x * blockDim.x + threadIdx.x;
    if (i < n_slots) g_counts[i] = 0.0f;
}

// ---------------------------------------------------------------------------
// Kernel 2: accumulate gated weights into counts.
// One thread per batch row; K atomics each (32768 total — negligible).
// ---------------------------------------------------------------------------
__global__ void k_accum_counts(const float* __restrict__ gate,
                               const int*   __restrict__ top_idx,
                               int B, int K) {
    int a = blockIdx.x * blockDim.x + threadIdx.x;
    if (a >= B) return;
    float g = gate[a];
    float w = (g > GATE_THRESH) ? g * UPDATE_RATE : 0.0f;
    if (w <= 0.0f) return;
    #pragma unroll
    for (int k = 0; k < 8; k++) {
        if (k < K) atomicAdd(&g_counts[top_idx[a * K + k]], w);
    }
}

// ---------------------------------------------------------------------------
// Kernel 3: dense base pass.  out_keys = mem_keys + 0.9*key_mom,
//                             out_vals = mem_vals + 0.9*val_mom.
// float4-vectorized streaming; this is the traffic floor (192 MB).
// ---------------------------------------------------------------------------
__global__ void k_base(const float4* __restrict__ mk,
                       const float4* __restrict__ mv,
                       const float4* __restrict__ km,
                       const float4* __restrict__ vm,
                       float4* __restrict__ out,
                       int n4_per_half) {
    int i = blockIdx.x * blockDim.x + threadIdx.x;
    if (i >= n4_per_half) return;

    float4 a = mk[i];
    float4 m = km[i];
    float4 r;
    r.x = a.x + MOMENTUM * m.x;
    r.y = a.y + MOMENTUM * m.y;
    r.z = a.z + MOMENTUM * m.z;
    r.w = a.w + MOMENTUM * m.w;
    out[i] = r;

    float4 b  = mv[i];
    float4 m2 = vm[i];
    float4 r2;
    r2.x = b.x + MOMENTUM * m2.x;
    r2.y = b.y + MOMENTUM * m2.y;
    r2.z = b.z + MOMENTUM * m2.z;
    r2.w = b.w + MOMENTUM * m2.w;
    out[n4_per_half + i] = r2;
}

// ---------------------------------------------------------------------------
// Kernel 4: sparse scatter correction.
// One warp per (a,k) pair. Each lane owns 4 contiguous floats (128 = 32*4).
// Adds (0.1 * w[a] / counts[s]) * row into the already-written output with
// vector float4 atomics (sm_90+ native).
// ---------------------------------------------------------------------------
__global__ void k_scatter(const float* __restrict__ q,
                          const float* __restrict__ v,
                          const float* __restrict__ gate,
                          const int*   __restrict__ top_idx,
                          float* __restrict__ out,
                          int B, int K, int n_slots) {
    int gtid = blockIdx.x * blockDim.x + threadIdx.x;
    int pair = gtid >> 5;
    int lane = gtid & 31;
    if (pair >= B * K) return;

    int a = pair / K;
    float g = gate[a];
    float w = (g > GATE_THRESH) ? g * UPDATE_RATE : 0.0f;
    if (w <= 0.0f) return;

    int s = top_idx[pair];
    float c = g_counts[s];                 // guaranteed >= w > 0 here
    float scale = ONE_MINUS_MOMENTUM * w / c;

    const float4* q4 = reinterpret_cast<const float4*>(q + (size_t)a * DIM);
    const float4* v4 = reinterpret_cast<const float4*>(v + (size_t)a * DIM);

    float4 qv = q4[lane];
    float4 vv = v4[lane];

    float4 qs = make_float4(qv.x * scale, qv.y * scale, qv.z * scale, qv.w * scale);
    float4 vs = make_float4(vv.x * scale, vv.y * scale, vv.z * scale, vv.w * scale);

    float4* ok = reinterpret_cast<float4*>(out + (size_t)s * DIM) + lane;
    float4* ov = reinterpret_cast<float4*>(out + (size_t)n_slots * DIM + (size_t)s * DIM) + lane;

#if __CUDA_ARCH__ >= 900
    atomicAdd(ok, qs);
    atomicAdd(ov, vs);
#else
    float* okf = reinterpret_cast<float*>(ok);
    float* ovf = reinterpret_cast<float*>(ov);
    atomicAdd(okf + 0, qs.x); atomicAdd(okf + 1, qs.y);
    atomicAdd(okf + 2, qs.z); atomicAdd(okf + 3, qs.w);
    atomicAdd(ovf + 0, vs.x); atomicAdd(ovf + 1, vs.y);
    atomicAdd(ovf + 2, vs.z); atomicAdd(ovf + 3, vs.w);
#endif
}

// ---------------------------------------------------------------------------
// Launch: 4 graph-capturable kernel launches, stream-ordered.
// Inputs (metadata order):
//   0 memory_keys   [N,128] f32     4 gate_weights [B]    f32
//   1 memory_values [N,128] f32     5 top_indices  [B,K]  i32
//   2 write_query   [B,128] f32     6 key_momentum [N,128] f32
//   3 write_value   [B,128] f32     7 value_momentum [N,128] f32
// Output: concat(updated_keys, updated_values)  [2*N*128] f32
// ---------------------------------------------------------------------------
extern "C" void kernel_launch(void* const* d_in, const int* in_sizes, int n_in,
                              void* d_out, int out_size) {
    const float* mem_keys = (const float*)d_in[0];
    const float* mem_vals = (const float*)d_in[1];
    const float* wq       = (const float*)d_in[2];
    const float* wv       = (const float*)d_in[3];
    const float* gate     = (const float*)d_in[4];
    const int*   idx      = (const int*)  d_in[5];
    const float* key_mom  = (const float*)d_in[6];
    const float* val_mom  = (const float*)d_in[7];
    float* out            = (float*)d_out;

    const int n_slots = in_sizes[0] / DIM;   // 65536
    const int B       = in_sizes[4];         // 4096
    const int K       = in_sizes[5] / B;     // 8
    const int n4_half = n_slots * DIM / 4;   // 2,097,152 float4 per matrix

    // 1) zero counts
    k_zero_counts<<<(n_slots + 255) / 256, 256>>>(n_slots);

    // 2) accumulate gated weights per slot
    k_accum_counts<<<(B + 255) / 256, 256>>>(gate, idx, B, K);

    // 3) dense base pass (independent of 1/2; ordered on stream anyway)
    k_base<<<(n4_half + 255) / 256, 256>>>(
        (const float4*)mem_keys, (const float4*)mem_vals,
        (const float4*)key_mom,  (const float4*)val_mom,
        (float4*)out, n4_half);

    // 4) sparse correction into output (needs counts + base written)
    int total_threads = B * K * 32;
    k_scatter<<<(total_threads + 255) / 256, 256>>>(
        wq, wv, gate, idx, out, B, K, n_slots);
}

// round 3
// speedup vs baseline: 1.0937x; 1.0937x over previous
#include <cuda_runtime.h>
#include <cstdint>

#define DIM 128
#define NSLOT_MAX 65536
#define PAIR_MAX   65536   // B*K = 32768 actual; headroom

#define UPDATE_RATE        0.1f
#define ONE_MINUS_MOMENTUM 0.1f
#define MOMENTUM           0.9f
#define GATE_THRESH        0.01f

// Scratch (__device__ globals — no allocation):
__device__ float g_counts[NSLOT_MAX];  // per-slot sum of gated weights
__device__ int   g_head[NSLOT_MAX];    // per-slot linked-list head (pair id), -1 = empty
__device__ int   g_next[PAIR_MAX];     // next pair in slot's list

// ---------------------------------------------------------------------------
// Kernel 1: init counts + list heads
// ---------------------------------------------------------------------------
__global__ void k_init(int n_slots) {
    int i = blockIdx.x * blockDim.x + threadIdx.x;
    if (i < n_slots) {
        g_counts[i] = 0.0f;
        g_head[i]   = -1;
    }
}

// ---------------------------------------------------------------------------
// Kernel 2: build per-slot lists + weighted counts.
// One thread per (a,k) pair; inactive pairs (w==0) are simply never linked.
// ---------------------------------------------------------------------------
__global__ void k_build(const float* __restrict__ gate,
                        const int*   __restrict__ top_idx,
                        int n_pairs, int K) {
    int p = blockIdx.x * blockDim.x + threadIdx.x;
    if (p >= n_pairs) return;
    int a = p / K;
    float g = gate[a];
    float w = (g > GATE_THRESH) ? g * UPDATE_RATE : 0.0f;
    if (w <= 0.0f) return;
    int s = top_idx[p];
    atomicAdd(&g_counts[s], w);
    g_next[p] = atomicExch(&g_head[s], p);
}

// ---------------------------------------------------------------------------
// Kernel 3: fused dense pass + sparse correction.
// One warp per slot row. Lane l owns float4 #l of the 128-float row
// (32 lanes * 4 floats = 128). Walks the slot's pair list (warp-uniform),
// accumulating w_a * q[a] and w_a * v[a] in registers, then writes
//   out = mem + MOMENTUM*mom + (0.1/counts) * acc
// in a single store — no atomics on the output, no DRAM RMW.
// ---------------------------------------------------------------------------
__global__ __launch_bounds__(256)
void k_fused(const float4* __restrict__ mk,
             const float4* __restrict__ mv,
             const float4* __restrict__ km,
             const float4* __restrict__ vm,
             const float*  __restrict__ q,
             const float*  __restrict__ v,
             const float*  __restrict__ gate,
             float4* __restrict__ out,
             int n_slots, int K) {
    int gtid = blockIdx.x * blockDim.x + threadIdx.x;
    int s    = gtid >> 5;           // one warp per slot
    int lane = gtid & 31;
    if (s >= n_slots) return;

    const int R4 = DIM / 4;         // 32 float4 per row
    size_t row = (size_t)s * R4 + lane;

    // Dense streams (the traffic floor)
    float4 a  = mk[row];
    float4 m  = km[row];
    float4 b  = mv[row];
    float4 m2 = vm[row];

    // Sparse correction accumulators
    float4 acck = make_float4(0.f, 0.f, 0.f, 0.f);
    float4 accv = make_float4(0.f, 0.f, 0.f, 0.f);

    int   p   = g_head[s];      // broadcast load (all lanes same addr)
    float cnt = g_counts[s];

    #pragma unroll 1
    while (p >= 0) {
        int   ba = p / K;
        float w  = gate[ba] * UPDATE_RATE;   // active by construction
        const float4* q4 = reinterpret_cast<const float4*>(q + (size_t)ba * DIM);
        const float4* v4 = reinterpret_cast<const float4*>(v + (size_t)ba * DIM);
        float4 qq = q4[lane];
        float4 vv = v4[lane];
        acck.x = fmaf(w, qq.x, acck.x);
        acck.y = fmaf(w, qq.y, acck.y);
        acck.z = fmaf(w, qq.z, acck.z);
        acck.w = fmaf(w, qq.w, acck.w);
        accv.x = fmaf(w, vv.x, accv.x);
        accv.y = fmaf(w, vv.y, accv.y);
        accv.z = fmaf(w, vv.z, accv.z);
        accv.w = fmaf(w, vv.w, accv.w);
        p = g_next[p];
    }

    float corr = (cnt > 0.0f) ? (ONE_MINUS_MOMENTUM / cnt) : 0.0f;

    float4 rk;
    rk.x = fmaf(MOMENTUM, m.x,  fmaf(corr, acck.x, a.x));
    rk.y = fmaf(MOMENTUM, m.y,  fmaf(corr, acck.y, a.y));
    rk.z = fmaf(MOMENTUM, m.z,  fmaf(corr, acck.z, a.z));
    rk.w = fmaf(MOMENTUM, m.w,  fmaf(corr, acck.w, a.w));

    float4 rv;
    rv.x = fmaf(MOMENTUM, m2.x, fmaf(corr, accv.x, b.x));
    rv.y = fmaf(MOMENTUM, m2.y, fmaf(corr, accv.y, b.y));
    rv.z = fmaf(MOMENTUM, m2.z, fmaf(corr, accv.z, b.z));
    rv.w = fmaf(MOMENTUM, m2.w, fmaf(corr, accv.w, b.w));

    out[row] = rk;
    out[(size_t)n_slots * R4 + row] = rv;
}

// ---------------------------------------------------------------------------
// Launch: 3 graph-capturable kernel launches, stream-ordered.
// Inputs (metadata order):
//   0 memory_keys   [N,128] f32     4 gate_weights [B]     f32
//   1 memory_values [N,128] f32     5 top_indices  [B,K]   i32
//   2 write_query   [B,128] f32     6 key_momentum [N,128] f32
//   3 write_value   [B,128] f32     7 value_momentum [N,128] f32
// Output: concat(updated_keys, updated_values)  [2*N*128] f32
// ---------------------------------------------------------------------------
extern "C" void kernel_launch(void* const* d_in, const int* in_sizes, int n_in,
                              void* d_out, int out_size) {
    const float* mem_keys = (const float*)d_in[0];
    const float* mem_vals = (const float*)d_in[1];
    const float* wq       = (const float*)d_in[2];
    const float* wv       = (const float*)d_in[3];
    const float* gate     = (const float*)d_in[4];
    const int*   idx      = (const int*)  d_in[5];
    const float* key_mom  = (const float*)d_in[6];
    const float* val_mom  = (const float*)d_in[7];
    float* out            = (float*)d_out;

    const int n_slots = in_sizes[0] / DIM;   // 65536
    const int B       = in_sizes[4];         // 4096
    const int K       = in_sizes[5] / B;     // 8
    const int n_pairs = B * K;               // 32768

    // 1) init heads + counts
    k_init<<<(n_slots + 255) / 256, 256>>>(n_slots);

    // 2) build per-slot pair lists + weighted counts
    k_build<<<(n_pairs + 255) / 256, 256>>>(gate, idx, n_pairs, K);

    // 3) fused dense + correction pass: one warp per slot
    long long total_threads = (long long)n_slots * 32;
    int blocks = (int)((total_threads + 255) / 256);
    k_fused<<<blocks, 256>>>(
        (const float4*)mem_keys, (const float4*)mem_vals,
        (const float4*)key_mom,  (const float4*)val_mom,
        wq, wv, gate, (float4*)out, n_slots, K);
}